// round 15
// baseline (speedup 1.0000x reference)
#include <cuda_runtime.h>
#include <cuda_fp16.h>
#include <stdint.h>

#define NN 4096
#define SB 4

#define CSPLIT   2                    // column split factor
#define ROWS_PB  16                   // rows per block (4 warps x 4 rows)
#define COLS_PB  (NN / CSPLIT)        // 2048
#define NRG      (NN / ROWS_PB)       // 256 row-groups
#define ITERS    (COLS_PB / 128)      // 16 warp-steps of 128 contiguous cols
#define GRID     (NRG * CSPLIT)       // 512 blocks, all co-resident (<= 148*4)

// Scratch (allocation-free requirement => __device__ globals)
__device__ __align__(16) __half g_E [(size_t)NN * NN];   // exp(-C/eps)    [n][m]
__device__ __align__(16) __half g_Et[(size_t)NN * NN];   // transpose      [m][n]
__device__ __align__(16) float  g_u [SB * NN];
__device__ __align__(16) float  g_v [SB * NN];
__device__ __align__(16) float  g_part[CSPLIT * SB * NN]; // per-half partial sums
__device__ int g_cnt[NRG];              // row-group arrival counters (self-resetting)
__device__ unsigned g_bar;              // grid-barrier arrive counter (returns to 0)
__device__ volatile unsigned g_gen;     // grid-barrier generation (monotonic)

// ---------------------------------------------------------------------------
__device__ __forceinline__ uint32_t s2u(const void* p) {
    uint32_t a;
    asm("{ .reg .u64 t; cvta.to.shared.u64 t, %1; cvt.u32.u64 %0, t; }" : "=r"(a) : "l"(p));
    return a;
}

// Sense-reversing grid barrier. All GRID blocks are co-resident by
// construction. The trailing __threadfence() is load-bearing twice over:
// (a) acquire ordering, (b) gpu-scope fence emits CCTL.IVALL, invalidating
// this SM's L1 so .nc loads after the barrier can't see stale u/v lines.
__device__ __forceinline__ void grid_barrier() {
    __syncthreads();
    if (threadIdx.x == 0) {
        __threadfence();                      // publish this block's writes
        unsigned gen = g_gen;
        unsigned old = atomicAdd(&g_bar, 1);
        if (old == GRID - 1) {
            g_bar = 0;                        // safe: everyone has arrived
            __threadfence();
            g_gen = gen + 1;                  // release
        } else {
            while (g_gen == gen) __nanosleep(64);
        }
        __threadfence();                      // acquire + L1 invalidate
    }
    __syncthreads();
}

// ---------------------------------------------------------------------------
// K = exp(-C/eps) in fp16 + transpose. C is read with L2::evict_first so its
// 64 MB never displaces E/Et (which are written with L2::evict_last and stay
// resident across the entire replay -> passes never touch DRAM for E).
__global__ __launch_bounds__(256) void prep_kernel(const float* __restrict__ C,
                                                   const float* __restrict__ eps_p) {
    __shared__ __half tile[32][33];
    unsigned long long polF, polL;
    asm("createpolicy.fractional.L2::evict_first.b64 %0, 1.0;" : "=l"(polF));
    asm("createpolicy.fractional.L2::evict_last.b64 %0, 1.0;"  : "=l"(polL));
    const float scale = -1.4426950408889634f / eps_p[0];
    const int tx = threadIdx.x, ty = threadIdx.y;
    const int x  = blockIdx.x * 32 + tx;
    const int yb = blockIdx.y * 32;
#pragma unroll
    for (int j = 0; j < 32; j += 8) {
        int y = yb + ty + j;
        float c;
        asm("ld.global.nc.L2::cache_hint.f32 %0, [%1], %2;"
            : "=f"(c) : "l"(C + (size_t)y * NN + x), "l"(polF));
        __half h = __float2half(exp2f(c * scale));
        unsigned short hb = __half_as_ushort(h);
        asm volatile("st.global.L2::cache_hint.b16 [%0], %1, %2;"
                     :: "l"(&g_E[(size_t)y * NN + x]), "h"(hb), "l"(polL) : "memory");
        tile[ty + j][tx] = h;
    }
    __syncthreads();
    const int x2  = blockIdx.y * 32 + tx;
    const int yb2 = blockIdx.x * 32;
#pragma unroll
    for (int j = 0; j < 32; j += 8) {
        unsigned short hb = __half_as_ushort(tile[tx][ty + j]);
        asm volatile("st.global.L2::cache_hint.b16 [%0], %1, %2;"
                     :: "l"(&g_Et[(size_t)(yb2 + ty + j) * NN + x2]), "h"(hb), "l"(polL) : "memory");
    }
}

// ---------------------------------------------------------------------------
// Persistent Sinkhorn: init + 20 half-steps + finalize in ONE kernel.
// Per half-step: xout[s][n] = ab[s][n] / sum_m M[n][m] * xin[s][m]
//
// vs R13: (1) u-half staged in smem once per half-step -> inner loop does
// ONE conflict-free LDS.128 per batch instead of two LDGs (warp-LDG count
// per block drops 768 -> 320, clearing the LSU dispatch floor);
// (2) depth-2 double-buffered E prefetch -> 2x in-flight E bytes, covering
// L2 latency at the LTS cap. E loads keep L1::no_allocate + L2::evict_last.
__global__ __launch_bounds__(128, 4) void sinkhorn_kernel(
    const float* __restrict__ alpha, const float* __restrict__ beta,
    const float* __restrict__ eps_p, float* __restrict__ out)
{
    __shared__ __align__(16) float s_u[SB][COLS_PB];   // 32 KB staged u-half
    __shared__ int s_last;
    const int tid  = threadIdx.x;
    const int warp = tid >> 5;
    const int lane = tid & 31;
    const int rg   = blockIdx.x >> 1;      // row-group (0..255)
    const int q    = blockIdx.x & 1;       // column half
    const int row0 = rg * ROWS_PB + warp * 4;
    const int col0 = q * COLS_PB;

    unsigned long long pol;
    asm("createpolicy.fractional.L2::evict_last.b64 %0, 1.0;" : "=l"(pol));
    const uint32_t ubase = s2u(&s_u[0][0]);

    // init: u = 1 (32 elements per block covers SB*NN = 16384)
    if (tid < 32) g_u[blockIdx.x * 32 + tid] = 1.0f;
    grid_barrier();

    for (int half = 0; half < 20; ++half) {
        const int dir = half & 1;
        const __half* Mh   = dir ? g_Et : g_E;
        const float*  xin  = dir ? g_v  : g_u;
        float*        xout = dir ? g_u  : g_v;
        const float*  ab   = dir ? beta : alpha;

        // ---- stage this block's u-half into smem (64 warp-LDGs total) ----
        {
            const float4* src = reinterpret_cast<const float4*>(xin);
            const int c4 = col0 >> 2;                  // float4 offset of half
#pragma unroll
            for (int k = 0; k < 16; k++) {
                int idx = k * 128 + tid;               // 0..2047
                int s   = idx >> 9;                    // /512
                int c   = idx & 511;
                *reinterpret_cast<float4*>(&s_u[s][c << 2]) = src[s * (NN >> 2) + c4 + c];
            }
        }
        __syncthreads();

        unsigned long long acc[4][4];
#pragma unroll
        for (int r = 0; r < 4; r++)
#pragma unroll
            for (int s = 0; s < 4; s++) acc[r][s] = 0ull;

        // ---- main loop: depth-2 E prefetch, u from smem ----
        uint32_t eb[2][4][2];
        auto lde = [&](int it, uint32_t (&b)[4][2]) {
            const int ci = col0 + it * 128 + lane * 4;
#pragma unroll
            for (int r = 0; r < 4; r++)
                asm("ld.global.nc.L1::no_allocate.L2::cache_hint.v2.u32 {%0,%1}, [%2], %3;"
                    : "=r"(b[r][0]), "=r"(b[r][1])
                    : "l"(Mh + (size_t)(row0 + r) * NN + ci), "l"(pol));
        };
        lde(0, eb[0]);

#pragma unroll 2
        for (int it = 0; it < ITERS; ++it) {
            if (it + 1 < ITERS) lde(it + 1, eb[(it + 1) & 1]);

            const uint32_t uoff = (it * 128 + lane * 4) * 4;  // bytes within plane
            unsigned long long u01[SB], u23[SB];
#pragma unroll
            for (int s = 0; s < SB; s++)
                asm("ld.shared.v2.b64 {%0,%1}, [%2];"
                    : "=l"(u01[s]), "=l"(u23[s])
                    : "r"(ubase + s * (COLS_PB * 4) + uoff));

            uint32_t (&cur)[4][2] = eb[it & 1];
#pragma unroll
            for (int r = 0; r < 4; r++) {
                float2 fa = __half22float2(*reinterpret_cast<const __half2*>(&cur[r][0]));
                float2 fb = __half22float2(*reinterpret_cast<const __half2*>(&cur[r][1]));
                unsigned long long e01, e23;
                asm("mov.b64 %0, {%1, %2};" : "=l"(e01) : "f"(fa.x), "f"(fa.y));
                asm("mov.b64 %0, {%1, %2};" : "=l"(e23) : "f"(fb.x), "f"(fb.y));
#pragma unroll
                for (int s = 0; s < SB; s++) {
                    asm("fma.rn.f32x2 %0, %1, %2, %0;" : "+l"(acc[r][s]) : "l"(e01), "l"(u01[s]));
                    asm("fma.rn.f32x2 %0, %1, %2, %0;" : "+l"(acc[r][s]) : "l"(e23), "l"(u23[s]));
                }
            }
        }

        // warp reduce each (row, batch); lane0 writes the partial for this half
#pragma unroll
        for (int r = 0; r < 4; r++) {
#pragma unroll
            for (int s = 0; s < 4; s++) {
                float lo, hi;
                asm("mov.b64 {%0, %1}, %2;" : "=f"(lo), "=f"(hi) : "l"(acc[r][s]));
                float t = lo + hi;
#pragma unroll
                for (int o = 16; o; o >>= 1) t += __shfl_down_sync(0xffffffffu, t, o);
                if (lane == 0)
                    g_part[(q * SB + s) * NN + row0 + r] = t;
            }
        }

        // last-block-per-row-group: deterministic combine + divide
        __threadfence();
        __syncthreads();
        if (tid == 0) {
            int old = atomicAdd(&g_cnt[rg], 1);
            s_last = (old == CSPLIT - 1);
        }
        __syncthreads();
        if (s_last) {
            __threadfence();
            if (tid < ROWS_PB * SB) {            // 64 outputs
                int nl = tid >> 2;
                int s  = tid & 3;
                int n  = rg * ROWS_PB + nl;
                float t = __ldcv(&g_part[(0 * SB + s) * NN + n])
                        + __ldcv(&g_part[(1 * SB + s) * NN + n]);
                xout[s * NN + n] = __ldg(&ab[s * NN + n]) / t;
            }
            if (tid == 0) g_cnt[rg] = 0;         // self-clean for next half
        }

        grid_barrier();
    }

    // finalize: f = eps*log(v), g = eps*log(u)
    const float eps = eps_p[0];
    const int i = blockIdx.x * 128 + tid;        // 65536 threads >= 16384
    if (i < SB * NN) {
        float v = __ldcv(&g_v[i]);
        float u = __ldcv(&g_u[i]);
        out[i]           = eps * __logf(v);      // f
        out[SB * NN + i] = eps * __logf(u);      // g
    }
}

// ---------------------------------------------------------------------------
extern "C" void kernel_launch(void* const* d_in, const int* in_sizes, int n_in,
                              void* d_out, int out_size) {
    const float* alpha = (const float*)d_in[0];  // (4, 4096)
    const float* beta  = (const float*)d_in[1];  // (4, 4096)
    const float* C     = (const float*)d_in[2];  // (4096, 4096)
    const float* eps   = (const float*)d_in[3];  // scalar
    float* out = (float*)d_out;                  // f then g

    dim3 pb(32, 8), pg(NN / 32, NN / 32);
    prep_kernel<<<pg, pb>>>(C, eps);

    sinkhorn_kernel<<<GRID, 128>>>(alpha, beta, eps, out);
}